// round 5
// baseline (speedup 1.0000x reference)
#include <cuda_runtime.h>
#include <cuda_bf16.h>
#include <math.h>
#include <cstdint>

#define N_      16
#define C_      128
#define T_      16384
#define K_      64
#define KG_     73
#define TT_     128
#define TILES_  (T_ / TT_)   // 128
#define SL_     9            // 16*9 = 144 CTAs, 1/SM
#define EPSF    1e-12f

__device__ float g_vlad_part[SL_ * N_ * K_ * C_];
__device__ float g_asum_part[SL_ * N_ * K_];
__device__ float g_knorm[N_ * K_];

// ---- smem layout (bytes) ----
#define XS_HI   0        // x hi  [c=128][t=128] bf16, 256B rows, swizzled
#define XS_LO   32768
#define W_HI    65536    // W hi [k=80][c=128] bf16 (rows 73..79 zero)
#define W_LO    86016
#define SF_HI   106496   // soft hi [t=128][k=64] bf16, 128B rows, swizzled
#define SF_LO   122880
#define LG      139264   // logits f32 [t=128][84] rows 336B
#define NRMP    182272   // float [16][128]
#define SNINV   190464   // float [128]
#define ASW     190976   // float [16][80]
#define SMEM_SZ 196096

__device__ __forceinline__ void ldsm4(uint32_t a, uint32_t r[4]) {
    asm volatile("ldmatrix.sync.aligned.m8n8.x4.shared.b16 {%0,%1,%2,%3}, [%4];"
        : "=r"(r[0]), "=r"(r[1]), "=r"(r[2]), "=r"(r[3]) : "r"(a));
}
__device__ __forceinline__ void ldsm4t(uint32_t a, uint32_t r[4]) {
    asm volatile("ldmatrix.sync.aligned.m8n8.x4.trans.shared.b16 {%0,%1,%2,%3}, [%4];"
        : "=r"(r[0]), "=r"(r[1]), "=r"(r[2]), "=r"(r[3]) : "r"(a));
}
__device__ __forceinline__ void mma16816(float d[4], const uint32_t a[4], const uint32_t b[2]) {
    asm volatile("mma.sync.aligned.m16n8k16.row.col.f32.bf16.bf16.f32 "
        "{%0,%1,%2,%3}, {%4,%5,%6,%7}, {%8,%9}, {%0,%1,%2,%3};"
        : "+f"(d[0]), "+f"(d[1]), "+f"(d[2]), "+f"(d[3])
        : "r"(a[0]), "r"(a[1]), "r"(a[2]), "r"(a[3]), "r"(b[0]), "r"(b[1]));
}
__device__ __forceinline__ uint32_t ldsm_addr(uint32_t base, int row0, int colb0, int rs, int lane) {
    int g = lane >> 3, r = lane & 7;
    int row  = row0 + r + ((g & 2) << 2);
    int colb = colb0 + ((g & 1) << 4);
    return base + row * rs + (colb ^ ((row & 7) << 4));
}
__device__ __forceinline__ void hilo2(float z0, float z1, uint32_t& hw, uint32_t& lw) {
    __nv_bfloat16 h0 = __float2bfloat16(z0);
    __nv_bfloat16 h1 = __float2bfloat16(z1);
    __nv_bfloat16 l0 = __float2bfloat16(z0 - __bfloat162float(h0));
    __nv_bfloat16 l1 = __float2bfloat16(z1 - __bfloat162float(h1));
    hw = (uint32_t)__bfloat16_as_ushort(h0) | ((uint32_t)__bfloat16_as_ushort(h1) << 16);
    lw = (uint32_t)__bfloat16_as_ushort(l0) | ((uint32_t)__bfloat16_as_ushort(l1) << 16);
}

__global__ __launch_bounds__(512, 1)
void vlad_mma(const float* __restrict__ x, const float* __restrict__ conv_w) {
    extern __shared__ __align__(16) char smem[];
    uint32_t sb;
    asm("{ .reg .u64 t; cvta.to.shared.u64 t, %1; cvt.u32.u64 %0, t; }" : "=r"(sb) : "l"(smem));

    const int n = blockIdx.x, sl = blockIdx.y;
    const int tid = threadIdx.x, w = tid >> 5, lane = tid & 31;
    const int q = lane >> 2, qk = lane & 3;

    float* nrmp    = (float*)(smem + NRMP);
    float* sninv_s = (float*)(smem + SNINV);
    float* asw     = (float*)(smem + ASW);

    // ---- W -> smem hi/lo, swizzled [k=80][c=128], rows >= 73 zero ----
    for (int idx = tid; idx < 80 * 128; idx += 512) {
        int k = idx >> 7, c = idx & 127;
        float v = (k < KG_) ? conv_w[k * 128 + c] : 0.f;
        __nv_bfloat16 h = __float2bfloat16(v);
        __nv_bfloat16 l = __float2bfloat16(v - __bfloat162float(h));
        int phys = k * 256 + ((c * 2) ^ ((k & 7) << 4));
        *(__nv_bfloat16*)(smem + W_HI + phys) = h;
        *(__nv_bfloat16*)(smem + W_LO + phys) = l;
    }

    // GEMM1 role: wt = t-block, wk = k-cluster group ({0,1,2} or {3,4})
    const int wt = w & 7, wk = w >> 3;
    const int np0 = wk ? 3 : 0, npc = wk ? 2 : 3;
    // GEMM2 role: wk2 = k-block (16 each), wc = c-block (32 each)
    const int wk2 = w >> 2, wc = w & 3;
    // softmax role: thread t, contiguous k-range of 20
    const int st = tid >> 2, part = tid & 3;
    const int kbase = part * 20;
    const int kcnt   = (part == 3) ? 13 : 20;   // k < 73
    const int kcnt64 = (part == 3) ? 4  : 20;   // k < 64

    float acc2[4][4];
#pragma unroll
    for (int i = 0; i < 4; ++i)
#pragma unroll
        for (int j = 0; j < 4; ++j) acc2[i][j] = 0.f;
    float asumr[20];
#pragma unroll
    for (int j = 0; j < 20; ++j) asumr[j] = 0.f;

    const float* xb = x + (long)n * C_ * T_;

    for (int tile = sl; tile < TILES_; tile += SL_) {
        __syncthreads();   // prev GEMM2 done with XS/SF
        const int t0g = tile * TT_;

        // ---- load + hi/lo convert + norm partials (warp owns 8 c-rows) ----
        {
            float sqv[4] = {0.f, 0.f, 0.f, 0.f};
#pragma unroll
            for (int ci = 0; ci < 8; ++ci) {
                int c = 8 * w + ci;
                float4 v = *(const float4*)(xb + (long)c * T_ + t0g + 4 * lane);
                sqv[0] += v.x * v.x; sqv[1] += v.y * v.y;
                sqv[2] += v.z * v.z; sqv[3] += v.w * v.w;
                uint32_t hw0, lw0, hw1, lw1;
                hilo2(v.x, v.y, hw0, lw0);
                hilo2(v.z, v.w, hw1, lw1);
                int phys = c * 256 + ((8 * lane) ^ ((c & 7) << 4));
                *(uint2*)(smem + XS_HI + phys) = make_uint2(hw0, hw1);
                *(uint2*)(smem + XS_LO + phys) = make_uint2(lw0, lw1);
            }
            *(float4*)(nrmp + w * 128 + 4 * lane) = make_float4(sqv[0], sqv[1], sqv[2], sqv[3]);
        }
        __syncthreads();

        // ---- norms (warps 0-3) run concurrent with GEMM1 issue of other warps ----
        if (tid < 128) {
            float s = 0.f;
#pragma unroll
            for (int ww = 0; ww < 16; ++ww) s += nrmp[ww * 128 + tid];
            sninv_s[tid] = 1.f / fmaxf(sqrtf(s), EPSF);
        }

        // ---- GEMM1: lg[t][k] = sum_c x[t][c] W[k][c]; warp covers t 16wt.., k-group wk ----
        {
            float acc1[6][4];
#pragma unroll
            for (int i = 0; i < 6; ++i)
#pragma unroll
                for (int j = 0; j < 4; ++j) acc1[i][j] = 0.f;

#pragma unroll
            for (int kk = 0; kk < 8; ++kk) {
                uint32_t ah[4], al[4];
                ldsm4t(ldsm_addr(sb + XS_HI, 16 * kk, 32 * wt, 256, lane), ah);
                ldsm4t(ldsm_addr(sb + XS_LO, 16 * kk, 32 * wt, 256, lane), al);
#pragma unroll
                for (int i = 0; i < 3; ++i) {
                    if (i < npc) {
                        int np = np0 + i;
                        uint32_t bh[4], bl[4];
                        ldsm4(ldsm_addr(sb + W_HI, 16 * np, 32 * kk, 256, lane), bh);
                        ldsm4(ldsm_addr(sb + W_LO, 16 * np, 32 * kk, 256, lane), bl);
                        mma16816(acc1[2 * i],     ah, bh);
                        mma16816(acc1[2 * i + 1], ah, bh + 2);
                        mma16816(acc1[2 * i],     al, bh);
                        mma16816(acc1[2 * i + 1], al, bh + 2);
                        mma16816(acc1[2 * i],     ah, bl);
                        mma16816(acc1[2 * i + 1], ah, bl + 2);
                    }
                }
            }
            // store logits to LG [t][84] f32
            const int tA = 16 * wt + q, tB = tA + 8;
#pragma unroll
            for (int i = 0; i < 3; ++i) {
                if (i < npc) {
                    int np = np0 + i;
#pragma unroll
                    for (int h = 0; h < 2; ++h) {
                        int k = 16 * np + 8 * h + 2 * qk;
                        *(float2*)(smem + LG + tA * 336 + k * 4) =
                            make_float2(acc1[2 * i + h][0], acc1[2 * i + h][1]);
                        *(float2*)(smem + LG + tB * 336 + k * 4) =
                            make_float2(acc1[2 * i + h][2], acc1[2 * i + h][3]);
                    }
                }
            }
        }
        __syncthreads();

        // ---- softmax: thread = (t, 20 contiguous k) ----
        {
            const float* lgrow = (const float*)(smem + LG + st * 336);
            float ev[20];
            float m = -1e30f;
#pragma unroll
            for (int j = 0; j < 20; ++j) {
                if (j < kcnt) { ev[j] = lgrow[kbase + j]; m = fmaxf(m, ev[j]); }
            }
            m = fmaxf(m, __shfl_xor_sync(~0u, m, 1));
            m = fmaxf(m, __shfl_xor_sync(~0u, m, 2));
            const float ninv = sninv_s[st];
            float s = 0.f;
#pragma unroll
            for (int j = 0; j < 20; ++j) {
                if (j < kcnt) { ev[j] = __expf((ev[j] - m) * ninv); s += ev[j]; }
            }
            s += __shfl_xor_sync(~0u, s, 1);
            s += __shfl_xor_sync(~0u, s, 2);
            const float isum = 1.f / s;
            const int tsw = (st & 7) << 4;
#pragma unroll
            for (int j = 0; j < 20; j += 2) {
                if (j < kcnt64) {
                    float s0 = ev[j] * isum, s1 = ev[j + 1] * isum;
                    asumr[j] += s0; asumr[j + 1] += s1;
                    uint32_t hw, lw;
                    hilo2(s0 * ninv, s1 * ninv, hw, lw);
                    int k = kbase + j;
                    int phys = st * 128 + ((2 * k) ^ tsw);
                    *(uint32_t*)(smem + SF_HI + phys) = hw;
                    *(uint32_t*)(smem + SF_LO + phys) = lw;
                }
            }
        }
        __syncthreads();

        // ---- GEMM2: vlad[k][c] += soft_scaled[k][t] x[c][t]; warp = (k-block, c-block) ----
#pragma unroll
        for (int kk = 0; kk < 8; ++kk) {
            uint32_t ah[4], al[4];
            ldsm4t(ldsm_addr(sb + SF_HI, 16 * kk, 32 * wk2, 128, lane), ah);
            ldsm4t(ldsm_addr(sb + SF_LO, 16 * kk, 32 * wk2, 128, lane), al);
#pragma unroll
            for (int np = 0; np < 2; ++np) {
                uint32_t bh[4], bl[4];
                ldsm4(ldsm_addr(sb + XS_HI, 32 * wc + 16 * np, 32 * kk, 256, lane), bh);
                ldsm4(ldsm_addr(sb + XS_LO, 32 * wc + 16 * np, 32 * kk, 256, lane), bl);
                mma16816(acc2[2 * np],     ah, bh);
                mma16816(acc2[2 * np + 1], ah, bh + 2);
                mma16816(acc2[2 * np],     al, bh);
                mma16816(acc2[2 * np + 1], al, bh + 2);
                mma16816(acc2[2 * np],     ah, bl);
                mma16816(acc2[2 * np + 1], ah, bl + 2);
            }
        }
    }

    // ---- asum: reduce over t within warp (same part = lanes stride 4), then across warps ----
    __syncthreads();
#pragma unroll
    for (int j = 0; j < 20; ++j) {
        float v = asumr[j];
        v += __shfl_xor_sync(~0u, v, 4);
        v += __shfl_xor_sync(~0u, v, 8);
        v += __shfl_xor_sync(~0u, v, 16);
        if (lane < 4) asw[w * 80 + lane * 20 + j] = v;   // index = global k (k<64 valid)
    }
    __syncthreads();
    if (tid < 64) {
        float s = 0.f;
#pragma unroll
        for (int ww = 0; ww < 16; ++ww) s += asw[ww * 80 + tid];
        g_asum_part[((long)(sl * N_ + n)) * K_ + tid] = s;
    }

    // ---- drain acc2 ----
    {
        const int kA = 16 * wk2 + q, kB = kA + 8;
        float* gp = g_vlad_part + ((long)(sl * N_ + n)) * K_ * C_;
#pragma unroll
        for (int np = 0; np < 2; ++np)
#pragma unroll
            for (int h = 0; h < 2; ++h) {
                int c = 32 * wc + 16 * np + 8 * h + 2 * qk;
                *(float2*)(gp + (long)kA * C_ + c) = make_float2(acc2[2 * np + h][0], acc2[2 * np + h][1]);
                *(float2*)(gp + (long)kB * C_ + c) = make_float2(acc2[2 * np + h][2], acc2[2 * np + h][3]);
            }
    }
}

// ---- Reduce: one CTA per (n,k) ----
__global__ __launch_bounds__(128)
void vlad_reduce(const float* __restrict__ centroids,
                 const float* __restrict__ cwts,
                 float* __restrict__ out) {
    const int k = blockIdx.x, n = blockIdx.y;
    const int tid = threadIdx.x;

    __shared__ float red[128];
    __shared__ float scw;

    float v = 0.f;
    const float* base = g_vlad_part + (long)n * K_ * C_ + (long)k * C_ + tid;
    const long str = (long)N_ * K_ * C_;
#pragma unroll
    for (int sl = 0; sl < SL_; ++sl) v += base[sl * str];

    red[tid] = (tid < SL_) ? g_asum_part[((long)(tid * N_ + n)) * K_ + k] : 0.f;
    if (tid == 0) {
        float s = 0.f;
        for (int kk = 0; kk < K_; ++kk) s += cwts[kk] * cwts[kk];
        scw = 1.f / fmaxf(sqrtf(s), EPSF);
    }
    __syncthreads();
#pragma unroll
    for (int s = 64; s > 0; s >>= 1) { if (tid < s) red[tid] += red[tid + s]; __syncthreads(); }
    const float asumv = red[0];
    __syncthreads();

    v -= asumv * centroids[k * C_ + tid];

    red[tid] = v * v;
    __syncthreads();
#pragma unroll
    for (int s = 64; s > 0; s >>= 1) { if (tid < s) red[tid] += red[tid + s]; __syncthreads(); }
    const float ssq = red[0];

    const float scale = (1.f / fmaxf(sqrtf(ssq), EPSF)) * cwts[k] * scw;
    out[(long)n * K_ * C_ + (long)k * C_ + tid] = v * scale;
    if (tid == 0) g_knorm[n * K_ + k] = ssq * scale * scale;
}

__global__ __launch_bounds__(256)
void vlad_finalize(float* __restrict__ out) {
    const int n = blockIdx.x, tid = threadIdx.x;
    __shared__ float sginv;
    if (tid == 0) {
        float g = 0.f;
        for (int k = 0; k < K_; ++k) g += g_knorm[n * K_ + k];
        sginv = 1.f / fmaxf(sqrtf(g), EPSF);
    }
    __syncthreads();
    const float gi = sginv;
    float4* p = (float4*)(out + (long)n * K_ * C_);
    for (int i = tid; i < (K_ * C_) / 4; i += 256) {
        float4 v = p[i];
        v.x *= gi; v.y *= gi; v.z *= gi; v.w *= gi;
        p[i] = v;
    }
}

extern "C" void kernel_launch(void* const* d_in, const int* in_sizes, int n_in,
                              void* d_out, int out_size) {
    const float* x      = (const float*)d_in[0];
    const float* conv_w = (const float*)d_in[1];
    const float* cent   = (const float*)d_in[2];
    const float* cwts   = (const float*)d_in[3];
    float* out = (float*)d_out;

    cudaFuncSetAttribute(vlad_mma, cudaFuncAttributeMaxDynamicSharedMemorySize, SMEM_SZ);
    vlad_mma<<<dim3(N_, SL_), 512, SMEM_SZ>>>(x, conv_w);
    vlad_reduce<<<dim3(K_, N_), 128>>>(cent, cwts, out);
    vlad_finalize<<<N_, 256>>>(out);
}

// round 6
// speedup vs baseline: 1.3638x; 1.3638x over previous
#include <cuda_runtime.h>
#include <cuda_bf16.h>
#include <math.h>
#include <cstdint>

#define N_      16
#define C_      128
#define T_      16384
#define K_      64
#define KG_     73
#define TT_     128
#define TILES_  (T_ / TT_)   // 128
#define SL_     9            // 16*9 = 144 CTAs, 1/SM
#define EPSF    1e-12f

__device__ float g_vlad_part[SL_ * N_ * K_ * C_];
__device__ float g_asum_part[SL_ * N_ * K_];
__device__ float g_knorm[N_ * K_];

// ---- smem layout (bytes) ----
#define XS_HI   0        // x hi  [c=128][t=128] bf16, 256B rows, swizzled
#define XS_LO   32768
#define W_HI    65536    // W hi [k=80][c=128] bf16 (rows 73..79 zero)
#define W_LO    86016
#define SF_HI   106496   // soft hi [t=128][k=64] bf16, 128B rows, swizzled
#define SF_LO   122880
#define STG     139264   // f32 staging [c=128][t=128], 512B rows (65536B)
#define NRMP    204800   // float [8][128]
#define SNINV   208896   // float [128]
#define ASW     209408   // float [8][64]
#define SMEM_SZ 211456

__device__ __forceinline__ void ldsm4(uint32_t a, uint32_t r[4]) {
    asm volatile("ldmatrix.sync.aligned.m8n8.x4.shared.b16 {%0,%1,%2,%3}, [%4];"
        : "=r"(r[0]), "=r"(r[1]), "=r"(r[2]), "=r"(r[3]) : "r"(a));
}
__device__ __forceinline__ void ldsm4t(uint32_t a, uint32_t r[4]) {
    asm volatile("ldmatrix.sync.aligned.m8n8.x4.trans.shared.b16 {%0,%1,%2,%3}, [%4];"
        : "=r"(r[0]), "=r"(r[1]), "=r"(r[2]), "=r"(r[3]) : "r"(a));
}
__device__ __forceinline__ void mma16816(float d[4], const uint32_t a[4], const uint32_t b[2]) {
    asm volatile("mma.sync.aligned.m16n8k16.row.col.f32.bf16.bf16.f32 "
        "{%0,%1,%2,%3}, {%4,%5,%6,%7}, {%8,%9}, {%0,%1,%2,%3};"
        : "+f"(d[0]), "+f"(d[1]), "+f"(d[2]), "+f"(d[3])
        : "r"(a[0]), "r"(a[1]), "r"(a[2]), "r"(a[3]), "r"(b[0]), "r"(b[1]));
}
__device__ __forceinline__ uint32_t ldsm_addr(uint32_t base, int row0, int colb0, int rs, int lane) {
    int g = lane >> 3, r = lane & 7;
    int row  = row0 + r + ((g & 2) << 2);
    int colb = colb0 + ((g & 1) << 4);
    return base + row * rs + (colb ^ ((row & 7) << 4));
}
// pack hi bf16x2 + residual lo bf16x2 (2 cvt + 2 alu + 2 sub)
__device__ __forceinline__ void hilo2(float z0, float z1, uint32_t& hw, uint32_t& lw) {
    uint32_t h;
    asm("cvt.rn.bf16x2.f32 %0, %2, %1;" : "=r"(h) : "f"(z0), "f"(z1));
    float f0 = __uint_as_float(h << 16);
    float f1 = __uint_as_float(h & 0xFFFF0000u);
    uint32_t l;
    asm("cvt.rn.bf16x2.f32 %0, %2, %1;" : "=r"(l) : "f"(z0 - f0), "f"(z1 - f1));
    hw = h; lw = l;
}
// packed dual FMA for norm accumulation
__device__ __forceinline__ float2 ffma2(float2 a, float2 b, float2 c) {
    float2 d;
    asm("fma.rn.f32x2 %0, %1, %2, %3;"
        : "=l"(*(unsigned long long*)&d)
        : "l"(*(unsigned long long*)&a),
          "l"(*(unsigned long long*)&b),
          "l"(*(unsigned long long*)&c));
    return d;
}
#define CP16(dst, src) asm volatile("cp.async.cg.shared.global [%0], [%1], 16;" :: "r"(dst), "l"(src))
#define CP_COMMIT()    asm volatile("cp.async.commit_group;" ::: "memory")
#define CP_WAIT0()     asm volatile("cp.async.wait_group 0;" ::: "memory")

__global__ __launch_bounds__(256, 1)
void vlad_mma(const float* __restrict__ x, const float* __restrict__ conv_w) {
    extern __shared__ __align__(16) char smem[];
    uint32_t sb;
    asm("{ .reg .u64 t; cvta.to.shared.u64 t, %1; cvt.u32.u64 %0, t; }" : "=r"(sb) : "l"(smem));

    const int n = blockIdx.x, sl = blockIdx.y;
    const int tid = threadIdx.x, w = tid >> 5, lane = tid & 31;
    const int q = lane >> 2, qk = lane & 3;

    float* nrmp    = (float*)(smem + NRMP);
    float* sninv_s = (float*)(smem + SNINV);
    float* asw     = (float*)(smem + ASW);

    // ---- W -> smem hi/lo, swizzled [k=80][c=128], rows >= 73 zero ----
    for (int idx = tid; idx < 80 * 128; idx += 256) {
        int k = idx >> 7, c = idx & 127;
        float v = (k < KG_) ? conv_w[k * 128 + c] : 0.f;
        __nv_bfloat16 h = __float2bfloat16(v);
        __nv_bfloat16 l = __float2bfloat16(v - __bfloat162float(h));
        int phys = k * 256 + ((c * 2) ^ ((k & 7) << 4));
        *(__nv_bfloat16*)(smem + W_HI + phys) = h;
        *(__nv_bfloat16*)(smem + W_LO + phys) = l;
    }

    float acc2[8][4];
#pragma unroll
    for (int i = 0; i < 8; ++i)
#pragma unroll
        for (int j = 0; j < 4; ++j) acc2[i][j] = 0.f;
    float asum_[8][2];
#pragma unroll
    for (int i = 0; i < 8; ++i) { asum_[i][0] = 0.f; asum_[i][1] = 0.f; }

    const float* xb = x + (long)n * C_ * T_;
    const int mcol1 = 32 * w;
    const int mcol2 = 32 * (w >> 1);
    const int nh2   = 64 * (w & 1);
    const int srow  = tid >> 5;       // staging row group
    const int scol  = (lane) * 16;    // staging byte col

    // ---- prologue: prefetch first tile ----
    {
        const int t0g = sl * TT_;
#pragma unroll
        for (int p = 0; p < 16; ++p) {
            int c = srow + 8 * p;
            CP16(sb + STG + c * 512 + scol,
                 (const void*)(xb + (long)c * T_ + t0g + 4 * lane));
        }
        CP_COMMIT();
    }

    for (int tile = sl; tile < TILES_; tile += SL_) {
        CP_WAIT0();
        __syncthreads();   // staging visible; prev GEMM2 done with XS/SF

        // ---- convert staging -> XS hi/lo + norm partials (warp owns 16 c-rows) ----
        {
            float2 sqA = make_float2(0.f, 0.f), sqB = make_float2(0.f, 0.f);
#pragma unroll
            for (int ci = 0; ci < 16; ++ci) {
                int c = 16 * w + ci;
                float4 v = *(const float4*)(smem + STG + c * 512 + 16 * lane);
                float2 p0 = make_float2(v.x, v.y), p1 = make_float2(v.z, v.w);
                sqA = ffma2(p0, p0, sqA);
                sqB = ffma2(p1, p1, sqB);
                uint32_t hw0, lw0, hw1, lw1;
                hilo2(v.x, v.y, hw0, lw0);
                hilo2(v.z, v.w, hw1, lw1);
                int phys = c * 256 + ((8 * lane) ^ ((c & 7) << 4));
                *(uint2*)(smem + XS_HI + phys) = make_uint2(hw0, hw1);
                *(uint2*)(smem + XS_LO + phys) = make_uint2(lw0, lw1);
            }
            *(float4*)(nrmp + w * 128 + 4 * lane) = make_float4(sqA.x, sqA.y, sqB.x, sqB.y);
        }
        __syncthreads();   // staging consumed; XS + nrmp ready

        // ---- prefetch next tile (overlaps GEMM1/softmax/GEMM2) ----
        {
            const int nt = tile + SL_;
            if (nt < TILES_) {
                const int t0g = nt * TT_;
#pragma unroll
                for (int p = 0; p < 16; ++p) {
                    int c = srow + 8 * p;
                    CP16(sb + STG + c * 512 + scol,
                         (const void*)(xb + (long)c * T_ + t0g + 4 * lane));
                }
            }
            CP_COMMIT();
        }

        // ---- norms ----
        if (tid < 128) {
            float s = 0.f;
#pragma unroll
            for (int ww = 0; ww < 8; ++ww) s += nrmp[ww * 128 + tid];
            sninv_s[tid] = 1.f / fmaxf(sqrtf(s), EPSF);
        }
        __syncthreads();   // sninv ready

        // ---- GEMM1: lg[t][kc], warp w owns t 16w..16w+15, all k ----
        float acc1[10][4];
#pragma unroll
        for (int i = 0; i < 10; ++i)
#pragma unroll
            for (int j = 0; j < 4; ++j) acc1[i][j] = 0.f;

#pragma unroll
        for (int kk = 0; kk < 8; ++kk) {
            uint32_t ah[4], al[4];
            ldsm4t(ldsm_addr(sb + XS_HI, 16 * kk, mcol1, 256, lane), ah);
            ldsm4t(ldsm_addr(sb + XS_LO, 16 * kk, mcol1, 256, lane), al);
#pragma unroll
            for (int np = 0; np < 5; ++np) {
                uint32_t bh[4], bl[4];
                ldsm4(ldsm_addr(sb + W_HI, 16 * np, 32 * kk, 256, lane), bh);
                ldsm4(ldsm_addr(sb + W_LO, 16 * np, 32 * kk, 256, lane), bl);
                mma16816(acc1[2 * np],     ah, bh);
                mma16816(acc1[2 * np + 1], ah, bh + 2);
                mma16816(acc1[2 * np],     al, bh);
                mma16816(acc1[2 * np + 1], al, bh + 2);
                mma16816(acc1[2 * np],     ah, bl);
                mma16816(acc1[2 * np + 1], ah, bl + 2);
            }
        }

        // ---- softmax (in-register; rows tA=16w+q, tB=tA+8); ghosts 64..72 ----
        {
            const int tA = 16 * w + q, tB = tA + 8;
            const float ninvA = sninv_s[tA], ninvB = sninv_s[tB];
            float mA = -1e30f, mB = -1e30f;
#pragma unroll
            for (int nn = 0; nn < 9; ++nn) {
                mA = fmaxf(mA, fmaxf(acc1[nn][0], acc1[nn][1]));
                mB = fmaxf(mB, fmaxf(acc1[nn][2], acc1[nn][3]));
            }
            if (qk == 0) { mA = fmaxf(mA, acc1[9][0]); mB = fmaxf(mB, acc1[9][2]); }
            mA = fmaxf(mA, __shfl_xor_sync(~0u, mA, 1));
            mA = fmaxf(mA, __shfl_xor_sync(~0u, mA, 2));
            mB = fmaxf(mB, __shfl_xor_sync(~0u, mB, 1));
            mB = fmaxf(mB, __shfl_xor_sync(~0u, mB, 2));

            float sA = 0.f, sB = 0.f;
#pragma unroll
            for (int nn = 0; nn < 9; ++nn) {
                acc1[nn][0] = __expf((acc1[nn][0] - mA) * ninvA); sA += acc1[nn][0];
                acc1[nn][1] = __expf((acc1[nn][1] - mA) * ninvA); sA += acc1[nn][1];
                acc1[nn][2] = __expf((acc1[nn][2] - mB) * ninvB); sB += acc1[nn][2];
                acc1[nn][3] = __expf((acc1[nn][3] - mB) * ninvB); sB += acc1[nn][3];
            }
            if (qk == 0) {
                sA += __expf((acc1[9][0] - mA) * ninvA);
                sB += __expf((acc1[9][2] - mB) * ninvB);
            }
            sA += __shfl_xor_sync(~0u, sA, 1); sA += __shfl_xor_sync(~0u, sA, 2);
            sB += __shfl_xor_sync(~0u, sB, 1); sB += __shfl_xor_sync(~0u, sB, 2);
            const float isA = 1.f / sA, isB = 1.f / sB;

#pragma unroll
            for (int nn = 0; nn < 8; ++nn) {
                float s0 = acc1[nn][0] * isA, s1 = acc1[nn][1] * isA;
                float s2 = acc1[nn][2] * isB, s3 = acc1[nn][3] * isB;
                asum_[nn][0] += s0 + s2;
                asum_[nn][1] += s1 + s3;
                uint32_t hwA, lwA, hwB, lwB;
                hilo2(s0 * ninvA, s1 * ninvA, hwA, lwA);
                hilo2(s2 * ninvB, s3 * ninvB, hwB, lwB);
                int cbyte = 16 * nn + 4 * qk;
                int pA = tA * 128 + (cbyte ^ ((tA & 7) << 4));
                int pB = tB * 128 + (cbyte ^ ((tB & 7) << 4));
                *(uint32_t*)(smem + SF_HI + pA) = hwA;
                *(uint32_t*)(smem + SF_LO + pA) = lwA;
                *(uint32_t*)(smem + SF_HI + pB) = hwB;
                *(uint32_t*)(smem + SF_LO + pB) = lwB;
            }
        }
        __syncthreads();   // SF ready

        // ---- GEMM2: vlad[kc][c] += soft_scaled[kc][t] x[c][t]^T ----
#pragma unroll
        for (int kk = 0; kk < 8; ++kk) {
            uint32_t ah[4], al[4];
            ldsm4t(ldsm_addr(sb + SF_HI, 16 * kk, mcol2, 128, lane), ah);
            ldsm4t(ldsm_addr(sb + SF_LO, 16 * kk, mcol2, 128, lane), al);
#pragma unroll
            for (int np = 0; np < 4; ++np) {
                uint32_t bh[4], bl[4];
                ldsm4(ldsm_addr(sb + XS_HI, nh2 + 16 * np, 32 * kk, 256, lane), bh);
                ldsm4(ldsm_addr(sb + XS_LO, nh2 + 16 * np, 32 * kk, 256, lane), bl);
                mma16816(acc2[2 * np],     ah, bh);
                mma16816(acc2[2 * np + 1], ah, bh + 2);
                mma16816(acc2[2 * np],     al, bh);
                mma16816(acc2[2 * np + 1], al, bh + 2);
                mma16816(acc2[2 * np],     ah, bl);
                mma16816(acc2[2 * np + 1], ah, bl + 2);
            }
        }
    }

    // ---- asum reduce ----
    __syncthreads();
#pragma unroll
    for (int nn = 0; nn < 8; ++nn) {
#pragma unroll
        for (int e = 0; e < 2; ++e) {
            float v = asum_[nn][e];
            v += __shfl_xor_sync(~0u, v, 4);
            v += __shfl_xor_sync(~0u, v, 8);
            v += __shfl_xor_sync(~0u, v, 16);
            if (lane < 4) asw[w * 64 + 8 * nn + 2 * lane + e] = v;
        }
    }
    __syncthreads();
    if (tid < 64) {
        float s = 0.f;
#pragma unroll
        for (int ww = 0; ww < 8; ++ww) s += asw[ww * 64 + tid];
        g_asum_part[((long)(sl * N_ + n)) * K_ + tid] = s;
    }

    // ---- drain acc2 ----
    {
        const int kA = 16 * (w >> 1) + q, kB = kA + 8;
        float* gp = g_vlad_part + ((long)(sl * N_ + n)) * K_ * C_;
#pragma unroll
        for (int nn = 0; nn < 8; ++nn) {
            int c = nh2 + 8 * nn + 2 * qk;
            *(float2*)(gp + (long)kA * C_ + c) = make_float2(acc2[nn][0], acc2[nn][1]);
            *(float2*)(gp + (long)kB * C_ + c) = make_float2(acc2[nn][2], acc2[nn][3]);
        }
    }
}

// ---- Reduce: one CTA per (n,k) ----
__global__ __launch_bounds__(128)
void vlad_reduce(const float* __restrict__ centroids,
                 const float* __restrict__ cwts,
                 float* __restrict__ out) {
    const int k = blockIdx.x, n = blockIdx.y;
    const int tid = threadIdx.x;

    __shared__ float red[128];
    __shared__ float scw;

    float v = 0.f;
    const float* base = g_vlad_part + (long)n * K_ * C_ + (long)k * C_ + tid;
    const long str = (long)N_ * K_ * C_;
#pragma unroll
    for (int sl = 0; sl < SL_; ++sl) v += base[sl * str];

    red[tid] = (tid < SL_) ? g_asum_part[((long)(tid * N_ + n)) * K_ + k] : 0.f;
    if (tid == 0) {
        float s = 0.f;
        for (int kk = 0; kk < K_; ++kk) s += cwts[kk] * cwts[kk];
        scw = 1.f / fmaxf(sqrtf(s), EPSF);
    }
    __syncthreads();
#pragma unroll
    for (int s = 64; s > 0; s >>= 1) { if (tid < s) red[tid] += red[tid + s]; __syncthreads(); }
    const float asumv = red[0];
    __syncthreads();

    v -= asumv * centroids[k * C_ + tid];

    red[tid] = v * v;
    __syncthreads();
#pragma unroll
    for (int s = 64; s > 0; s >>= 1) { if (tid < s) red[tid] += red[tid + s]; __syncthreads(); }
    const float ssq = red[0];

    const float scale = (1.f / fmaxf(sqrtf(ssq), EPSF)) * cwts[k] * scw;
    out[(long)n * K_ * C_ + (long)k * C_ + tid] = v * scale;
    if (tid == 0) g_knorm[n * K_ + k] = ssq * scale * scale;
}

__global__ __launch_bounds__(256)
void vlad_finalize(float* __restrict__ out) {
    const int n = blockIdx.x, tid = threadIdx.x;
    __shared__ float sginv;
    if (tid == 0) {
        float g = 0.f;
        for (int k = 0; k < K_; ++k) g += g_knorm[n * K_ + k];
        sginv = 1.f / fmaxf(sqrtf(g), EPSF);
    }
    __syncthreads();
    const float gi = sginv;
    float4* p = (float4*)(out + (long)n * K_ * C_);
    for (int i = tid; i < (K_ * C_) / 4; i += 256) {
        float4 v = p[i];
        v.x *= gi; v.y *= gi; v.z *= gi; v.w *= gi;
        p[i] = v;
    }
}

extern "C" void kernel_launch(void* const* d_in, const int* in_sizes, int n_in,
                              void* d_out, int out_size) {
    const float* x      = (const float*)d_in[0];
    const float* conv_w = (const float*)d_in[1];
    const float* cent   = (const float*)d_in[2];
    const float* cwts   = (const float*)d_in[3];
    float* out = (float*)d_out;

    cudaFuncSetAttribute(vlad_mma, cudaFuncAttributeMaxDynamicSharedMemorySize, SMEM_SZ);
    vlad_mma<<<dim3(N_, SL_), 256, SMEM_SZ>>>(x, conv_w);
    vlad_reduce<<<dim3(K_, N_), 128>>>(cent, cwts, out);
    vlad_finalize<<<N_, 256>>>(out);
}